// round 13
// baseline (speedup 1.0000x reference)
#include <cuda_runtime.h>
#include <cuda_bf16.h>
#include <cuda_fp16.h>
#include <cstdint>

#define NN   100000
#define DEG  16
#define DIM  128
#define TM   96                       // rows per persistent-loop tile
#define NT   ((NN + TM - 1) / TM)     // 1042 tiles
#define GRIDP 148                     // persistent CTAs per output type

// ---------------- scratch (device globals: allocations are forbidden) ----------------
__device__ __half g_z [(size_t)NN * DIM];
__device__ __half g_zi[(size_t)NN * DIM];
__device__ __nv_bfloat16 g_h1hi[(size_t)NN * DIM];   // layer-1 output, pre-split
__device__ __nv_bfloat16 g_h1lo[(size_t)NN * DIM];
__device__ float g_ss[2][NN];         // partial ssrc per N-half
__device__ float g_sd[2][NN];         // partial sdst per N-half
__device__ __nv_bfloat16 g_wimg[4][2][DIM * DIM];    // [W1,U1,W2,U2][hi/lo] row-major

// ---------------- helpers ----------------
__device__ __forceinline__ uint32_t smem_to_u32(const void* p) {
    uint32_t a;
    asm("{ .reg .u64 t; cvta.to.shared.u64 t, %1; cvt.u32.u64 %0, t; }" : "=r"(a) : "l"(p));
    return a;
}
__device__ __forceinline__ void ldsm4(uint32_t* r, uint32_t addr) {
    asm volatile("ldmatrix.sync.aligned.m8n8.x4.shared.b16 {%0,%1,%2,%3}, [%4];"
                 : "=r"(r[0]), "=r"(r[1]), "=r"(r[2]), "=r"(r[3]) : "r"(addr));
}
__device__ __forceinline__ void mma16816(float* d, const uint32_t* a, const uint32_t* b) {
    asm volatile("mma.sync.aligned.m16n8k16.row.col.f32.bf16.bf16.f32 "
                 "{%0,%1,%2,%3}, {%4,%5,%6,%7}, {%8,%9}, {%0,%1,%2,%3};"
                 : "+f"(d[0]), "+f"(d[1]), "+f"(d[2]), "+f"(d[3])
                 : "r"(a[0]), "r"(a[1]), "r"(a[2]), "r"(a[3]), "r"(b[0]), "r"(b[1]));
}
// swizzled byte offset of 16B chunk q in row r (256 B rows, conflict-free for 8-lane LDSM wavefronts)
#define SWOFF(r, q) ((uint32_t)((r) * 256 + (((q) ^ ((r) & 7)) << 4)))

// ---------------- weight conversion (hi/lo bf16 split, row-major) ----------------
__global__ void wconv_kernel(const float* __restrict__ W1, const float* __restrict__ U1,
                             const float* __restrict__ W2, const float* __restrict__ U2)
{
    const int b = blockIdx.x;
    const float* src = (b == 0) ? W1 : (b == 1) ? U1 : (b == 2) ? W2 : U2;
    __nv_bfloat16* hi = g_wimg[b][0];
    __nv_bfloat16* lo = g_wimg[b][1];
    for (int c = threadIdx.x; c < DIM * DIM / 8; c += blockDim.x) {
        int row = c >> 4, cc = (c & 15) * 8;
        __align__(16) __nv_bfloat16 hb[8], lb[8];
        const float4* p = (const float4*)(src + row * DIM + cc);
        float4 v0 = p[0], v1 = p[1];
        float xs[8] = {v0.x, v0.y, v0.z, v0.w, v1.x, v1.y, v1.z, v1.w};
        #pragma unroll
        for (int j = 0; j < 8; j++) {
            __nv_bfloat16 h = __float2bfloat16(xs[j]);
            hb[j] = h;
            lb[j] = __float2bfloat16(xs[j] - __bfloat162float(h));
        }
        *(uint4*)(hi + row * DIM + cc) = *(const uint4*)hb;
        *(uint4*)(lo + row * DIM + cc) = *(const uint4*)lb;
    }
}

// ---------------- persistent split-output tensor-core GEMM ----------------
// CTA type z (bid<148): z = h@W^T (fp16) + partial scores; zi-CTA: zi = h@U^T.
// smem byte layout: W_hi[0,32K) W_lo[32K,64K) A_hi[64K,88K) A_lo[88K,112K)
#define SB_WH 0u
#define SB_WL 32768u
#define SB_AH 65536u
#define SB_AL 90112u
#define SM_TOTAL_B 114688

__global__ __launch_bounds__(192, 2)
void gemm_split_kernel(int mode,                       // 0: fp32 input, 1: pre-split bf16
                     const float* __restrict__ hf,
                     const __nv_bfloat16* __restrict__ hbh, const __nv_bfloat16* __restrict__ hbl,
                     const __nv_bfloat16* __restrict__ wh, const __nv_bfloat16* __restrict__ wl,
                     const __nv_bfloat16* __restrict__ uh, const __nv_bfloat16* __restrict__ ul,
                     const float* __restrict__ avec,
                     __half* __restrict__ z, __half* __restrict__ zi,
                     float* __restrict__ ss0, float* __restrict__ ss1,
                     float* __restrict__ sd0, float* __restrict__ sd1, int n)
{
    extern __shared__ char smem[];
    const int tid  = threadIdx.x;
    const int lane = tid & 31;
    const int wid  = tid >> 5;                 // 0..5
    const uint32_t sb = smem_to_u32(smem);

    const bool isU = (blockIdx.x >= GRIDP);
    const int  t0  = blockIdx.x - (isU ? GRIDP : 0);

    // ---- load this CTA's weight pair ONCE (swizzled copy) ----
    {
        const __nv_bfloat16* bhsrc = isU ? uh : wh;
        const __nv_bfloat16* blsrc = isU ? ul : wl;
        for (int c = tid; c < DIM * 16; c += 192) {
            int r = c >> 4, q = c & 15;
            uint32_t off = SWOFF(r, q);
            *(uint4*)(smem + SB_WH + off) = *(const uint4*)(bhsrc + r * DIM + q * 8);
            *(uint4*)(smem + SB_WL + off) = *(const uint4*)(blsrc + r * DIM + q * 8);
        }
    }

    // warp tiling: 3 M-warps x 2 N-warps, warp tile 32(M)x64(N)
    const int mw = wid % 3, nw = wid / 3;
    const int m0 = mw * 32;
    const int n0 = nw * 64;
    const int a_r = (lane & 15);
    const int acq = (lane >> 4);               // A chunk half
    const int b_r = ((lane >> 4) << 3) + (lane & 7);
    const int bcq = ((lane >> 3) & 1);         // B chunk half

    __half* dst = isU ? zi : z;
    float* ssP = nw ? ss1 : ss0;
    float* sdP = nw ? sd1 : sd0;

    // score vectors for this warp's 64 cols (hoisted; z-CTAs use them)
    float asv[8][2], adv[8][2];
    #pragma unroll
    for (int nf = 0; nf < 8; nf++) {
        const int c = n0 + nf * 8 + (lane & 3) * 2;
        asv[nf][0] = avec[c];       asv[nf][1] = avec[c + 1];
        adv[nf][0] = avec[DIM + c]; adv[nf][1] = avec[DIM + c + 1];
    }

    for (int t = t0; t < NT; t += GRIDP) {
        const int row0 = t * TM;

        // ---- fill A smem (hi/lo, swizzled): 96x16 chunks, 8 per thread ----
        if (mode == 0) {
            #pragma unroll
            for (int i = 0; i < 8; i++) {
                int c = tid + i * 192;
                int r = c >> 4, q = c & 15;
                int gr = row0 + r;
                __align__(16) __nv_bfloat16 hb[8], lb[8];
                if (gr < n) {
                    const float4* p = (const float4*)(hf + (size_t)gr * DIM + q * 8);
                    float4 v0 = p[0], v1 = p[1];
                    float xs[8] = {v0.x, v0.y, v0.z, v0.w, v1.x, v1.y, v1.z, v1.w};
                    #pragma unroll
                    for (int j = 0; j < 8; j++) {
                        __nv_bfloat16 hv = __float2bfloat16(xs[j]);
                        hb[j] = hv;
                        lb[j] = __float2bfloat16(xs[j] - __bfloat162float(hv));
                    }
                } else {
                    #pragma unroll
                    for (int j = 0; j < 8; j++) { hb[j] = __float2bfloat16(0.f); lb[j] = hb[j]; }
                }
                uint32_t off = SWOFF(r, q);
                *(uint4*)(smem + SB_AH + off) = *(const uint4*)hb;
                *(uint4*)(smem + SB_AL + off) = *(const uint4*)lb;
            }
        } else {
            #pragma unroll
            for (int i = 0; i < 8; i++) {
                int c = tid + i * 192;
                int r = c >> 4, q = c & 15;
                int gr = row0 + r;
                uint4 vh = make_uint4(0, 0, 0, 0), vl = vh;
                if (gr < n) {
                    vh = *(const uint4*)(hbh + (size_t)gr * DIM + q * 8);
                    vl = *(const uint4*)(hbl + (size_t)gr * DIM + q * 8);
                }
                uint32_t off = SWOFF(r, q);
                *(uint4*)(smem + SB_AH + off) = vh;
                *(uint4*)(smem + SB_AL + off) = vl;
            }
        }
        __syncthreads();

        // ---- MMA: warp tile 32x64, 3-split ----
        float acc[2][8][4];
        #pragma unroll
        for (int mf = 0; mf < 2; mf++)
            #pragma unroll
            for (int nf = 0; nf < 8; nf++)
                #pragma unroll
                for (int q = 0; q < 4; q++) acc[mf][nf][q] = 0.f;

        #pragma unroll
        for (int ks = 0; ks < 8; ks++) {
            uint32_t ah[2][4], al[2][4];
            #pragma unroll
            for (int mf = 0; mf < 2; mf++) {
                const int ar = m0 + mf * 16 + a_r;
                const uint32_t aoff = SWOFF(ar, 2 * ks + acq);
                ldsm4(ah[mf], sb + SB_AH + aoff);
                ldsm4(al[mf], sb + SB_AL + aoff);
            }
            #pragma unroll
            for (int np = 0; np < 4; np++) {
                const int br = n0 + np * 16 + b_r;
                const uint32_t boff = SWOFF(br, 2 * ks + bcq);
                uint32_t bh[4], bl[4];
                ldsm4(bh, sb + SB_WH + boff);
                ldsm4(bl, sb + SB_WL + boff);
                #pragma unroll
                for (int mf = 0; mf < 2; mf++) {
                    mma16816(acc[mf][2 * np + 0], ah[mf], &bh[0]);
                    mma16816(acc[mf][2 * np + 0], ah[mf], &bl[0]);
                    mma16816(acc[mf][2 * np + 0], al[mf], &bh[0]);
                    mma16816(acc[mf][2 * np + 1], ah[mf], &bh[2]);
                    mma16816(acc[mf][2 * np + 1], ah[mf], &bl[2]);
                    mma16816(acc[mf][2 * np + 1], al[mf], &bh[2]);
                }
            }
        }

        // ---- epilogue: fp16 STG ----
        #pragma unroll
        for (int mf = 0; mf < 2; mf++) {
            const int mA = row0 + m0 + mf * 16 + (lane >> 2);
            #pragma unroll
            for (int nf = 0; nf < 8; nf++) {
                const int c = n0 + nf * 8 + (lane & 3) * 2;
                if (mA < n)
                    *(__half2*)(dst + (size_t)mA * DIM + c) =
                        __floats2half2_rn(acc[mf][nf][0], acc[mf][nf][1]);
                if (mA + 8 < n)
                    *(__half2*)(dst + (size_t)(mA + 8) * DIM + c) =
                        __floats2half2_rn(acc[mf][nf][2], acc[mf][nf][3]);
            }
        }

        // ---- partial scores from z accumulators (z-CTAs only) ----
        if (!isU) {
            #pragma unroll
            for (int mf = 0; mf < 2; mf++) {
                float s0 = 0.f, s1 = 0.f, d0 = 0.f, d1 = 0.f;
                #pragma unroll
                for (int nf = 0; nf < 8; nf++) {
                    s0 += acc[mf][nf][0] * asv[nf][0] + acc[mf][nf][1] * asv[nf][1];
                    s1 += acc[mf][nf][2] * asv[nf][0] + acc[mf][nf][3] * asv[nf][1];
                    d0 += acc[mf][nf][0] * adv[nf][0] + acc[mf][nf][1] * adv[nf][1];
                    d1 += acc[mf][nf][2] * adv[nf][0] + acc[mf][nf][3] * adv[nf][1];
                }
                #pragma unroll
                for (int o = 1; o <= 2; o <<= 1) {
                    s0 += __shfl_xor_sync(0xffffffffu, s0, o);
                    s1 += __shfl_xor_sync(0xffffffffu, s1, o);
                    d0 += __shfl_xor_sync(0xffffffffu, d0, o);
                    d1 += __shfl_xor_sync(0xffffffffu, d1, o);
                }
                if ((lane & 3) == 0) {
                    const int r = row0 + m0 + mf * 16 + (lane >> 2);
                    if (r < n)     { ssP[r] = s0;     sdP[r] = d0; }
                    if (r + 8 < n) { ssP[r + 8] = s1; sdP[r + 8] = d1; }
                }
            }
        }
        __syncthreads();   // all LDSM done before next tile's A overwrite
    }
}

// ---------------- attention + aggregation (fp16 gather, split-score sum) ----------------
__global__ __launch_bounds__(256)
void attn_agg_kernel(const __half* __restrict__ z, const __half* __restrict__ zi,
                     const float* __restrict__ ss0, const float* __restrict__ ss1,
                     const float* __restrict__ sd0, const float* __restrict__ sd1,
                     const float* __restrict__ edge_d, const int* __restrict__ edge_src,
                     const float* __restrict__ Wv, const float* __restrict__ avec,
                     int toSplit,
                     __nv_bfloat16* __restrict__ outHi, __nv_bfloat16* __restrict__ outLo,
                     float* __restrict__ outF, int n)
{
    const int node = (blockIdx.x * blockDim.x + threadIdx.x) >> 5;
    const int lane = threadIdx.x & 31;
    if (node >= n) return;

    const float c = Wv[0] * avec[2 * DIM];

    int   src = 0;
    float sc  = -1e30f;
    if (lane < DEG) {
        int e = node * DEG + lane;
        src   = edge_src[e];
        float s = (ss0[src] + ss1[src]) + (sd0[node] + sd1[node]) + c * edge_d[e];
        sc = (s >= 0.f) ? s : 0.01f * s;
    }
    float m = sc;
    #pragma unroll
    for (int o = 8; o > 0; o >>= 1) m = fmaxf(m, __shfl_xor_sync(0xffffffffu, m, o));
    float ex = (lane < DEG) ? __expf(sc - m) : 0.f;
    float ssum = ex;
    #pragma unroll
    for (int o = 8; o > 0; o >>= 1) ssum += __shfl_xor_sync(0xffffffffu, ssum, o);
    float alpha = ex / ssum;

    float al[DEG];
    int   sr[DEG];
    #pragma unroll
    for (int e = 0; e < DEG; e++) {
        al[e] = __shfl_sync(0xffffffffu, alpha, e);
        sr[e] = __shfl_sync(0xffffffffu, src,   e);
    }

    float4 acc;
    {
        uint2 v = *((const uint2*)(zi + (size_t)node * DIM) + lane);
        float2 f0 = __half22float2(*(__half2*)&v.x);
        float2 f1 = __half22float2(*(__half2*)&v.y);
        acc = make_float4(f0.x, f0.y, f1.x, f1.y);
    }
    #pragma unroll
    for (int e = 0; e < DEG; e++) {
        uint2 v = *((const uint2*)(z + (size_t)sr[e] * DIM) + lane);
        float2 f0 = __half22float2(*(__half2*)&v.x);
        float2 f1 = __half22float2(*(__half2*)&v.y);
        acc.x = fmaf(al[e], f0.x, acc.x);
        acc.y = fmaf(al[e], f0.y, acc.y);
        acc.z = fmaf(al[e], f1.x, acc.z);
        acc.w = fmaf(al[e], f1.y, acc.w);
    }
    acc.x = fmaxf(acc.x, 0.f);
    acc.y = fmaxf(acc.y, 0.f);
    acc.z = fmaxf(acc.z, 0.f);
    acc.w = fmaxf(acc.w, 0.f);

    if (toSplit) {
        // write h1 pre-split (bf16 hi/lo) for the layer-2 GEMM
        float xs[4] = {acc.x, acc.y, acc.z, acc.w};
        __align__(8) __nv_bfloat16 hb[4], lb[4];
        #pragma unroll
        for (int j = 0; j < 4; j++) {
            __nv_bfloat16 hv = __float2bfloat16(xs[j]);
            hb[j] = hv;
            lb[j] = __float2bfloat16(xs[j] - __bfloat162float(hv));
        }
        *(uint2*)(outHi + (size_t)node * DIM + lane * 4) = *(const uint2*)hb;
        *(uint2*)(outLo + (size_t)node * DIM + lane * 4) = *(const uint2*)lb;
    } else {
        *(float4*)(outF + (size_t)node * DIM + lane * 4) = acc;
    }
}

extern "C" void kernel_launch(void* const* d_in, const int* in_sizes, int n_in,
                              void* d_out, int out_size)
{
    const float* attr   = (const float*)d_in[0];
    const float* edge_d = (const float*)d_in[1];
    const float* Wv1    = (const float*)d_in[2];
    const float* Ww1    = (const float*)d_in[3];
    const float* Wu1    = (const float*)d_in[4];
    const float* Wa1    = (const float*)d_in[5];
    const float* Wv2    = (const float*)d_in[6];
    const float* Ww2    = (const float*)d_in[7];
    const float* Wu2    = (const float*)d_in[8];
    const float* Wa2    = (const float*)d_in[9];
    const int*   esrc   = (const int*)d_in[10];
    float*       out    = (float*)d_out;

    float *ssp, *sdp;
    __half *zp, *zip;
    __nv_bfloat16 *wb, *h1h, *h1l;
    cudaGetSymbolAddress((void**)&zp,  g_z);
    cudaGetSymbolAddress((void**)&zip, g_zi);
    cudaGetSymbolAddress((void**)&h1h, g_h1hi);
    cudaGetSymbolAddress((void**)&h1l, g_h1lo);
    cudaGetSymbolAddress((void**)&ssp, g_ss);
    cudaGetSymbolAddress((void**)&sdp, g_sd);
    cudaGetSymbolAddress((void**)&wb,  g_wimg);

    float* ss0 = ssp;           float* ss1 = ssp + NN;
    float* sd0 = sdp;           float* sd1 = sdp + NN;

    const __nv_bfloat16* w1h = wb + (size_t)0 * DIM * DIM;
    const __nv_bfloat16* w1l = wb + (size_t)1 * DIM * DIM;
    const __nv_bfloat16* u1h = wb + (size_t)2 * DIM * DIM;
    const __nv_bfloat16* u1l = wb + (size_t)3 * DIM * DIM;
    const __nv_bfloat16* w2h = wb + (size_t)4 * DIM * DIM;
    const __nv_bfloat16* w2l = wb + (size_t)5 * DIM * DIM;
    const __nv_bfloat16* u2h = wb + (size_t)6 * DIM * DIM;
    const __nv_bfloat16* u2l = wb + (size_t)7 * DIM * DIM;

    cudaFuncSetAttribute(gemm_split_kernel,
                         cudaFuncAttributeMaxDynamicSharedMemorySize, SM_TOTAL_B);

    const int grid_a = (NN * 32 + 255) / 256;     // 12500

    wconv_kernel<<<4, 256>>>(Ww1, Wu1, Ww2, Wu2);

    gemm_split_kernel<<<2 * GRIDP, 192, SM_TOTAL_B>>>(0, attr, nullptr, nullptr,
                                                      w1h, w1l, u1h, u1l, Wa1,
                                                      zp, zip, ss0, ss1, sd0, sd1, NN);
    attn_agg_kernel<<<grid_a, 256>>>(zp, zip, ss0, ss1, sd0, sd1, edge_d, esrc, Wv1, Wa1,
                                     1, h1h, h1l, nullptr, NN);

    gemm_split_kernel<<<2 * GRIDP, 192, SM_TOTAL_B>>>(1, nullptr, h1h, h1l,
                                                      w2h, w2l, u2h, u2l, Wa2,
                                                      zp, zip, ss0, ss1, sd0, sd1, NN);
    attn_agg_kernel<<<grid_a, 256>>>(zp, zip, ss0, ss1, sd0, sd1, edge_d, esrc, Wv2, Wa2,
                                     0, nullptr, nullptr, out, NN);
}

// round 14
// speedup vs baseline: 1.3551x; 1.3551x over previous
#include <cuda_runtime.h>
#include <cuda_bf16.h>
#include <cuda_fp16.h>
#include <cstdint>

#define NN   100000
#define DEG  16
#define DIM  128
#define PADS 136                      // padded smem row stride (fp16 elems)
#define TM   128                      // rows per persistent-loop tile
#define NT   ((NN + TM - 1) / TM)     // 782 tiles
#define GRIDP 148                     // persistent CTAs per output type

// ---------------- scratch (device globals: allocations are forbidden) ----------------
__device__ __half g_z [(size_t)NN * DIM];
__device__ __half g_zi[(size_t)NN * DIM];
__device__ __half g_h1[(size_t)NN * DIM];            // layer-1 output, fp16
__device__ float g_ssrc[NN];
__device__ float g_sdst[NN];
__device__ __half g_wimg[4][2][DIM * DIM];           // [W1,U1,W2,U2][hi/lo] fp16 row-major

// ---------------- helpers ----------------
__device__ __forceinline__ uint32_t smem_to_u32(const void* p) {
    uint32_t a;
    asm("{ .reg .u64 t; cvta.to.shared.u64 t, %1; cvt.u32.u64 %0, t; }" : "=r"(a) : "l"(p));
    return a;
}
__device__ __forceinline__ void ldsm4(uint32_t* r, uint32_t addr) {
    asm volatile("ldmatrix.sync.aligned.m8n8.x4.shared.b16 {%0,%1,%2,%3}, [%4];"
                 : "=r"(r[0]), "=r"(r[1]), "=r"(r[2]), "=r"(r[3]) : "r"(addr));
}
__device__ __forceinline__ void mma16816h(float* d, const uint32_t* a, const uint32_t* b) {
    asm volatile("mma.sync.aligned.m16n8k16.row.col.f32.f16.f16.f32 "
                 "{%0,%1,%2,%3}, {%4,%5,%6,%7}, {%8,%9}, {%0,%1,%2,%3};"
                 : "+f"(d[0]), "+f"(d[1]), "+f"(d[2]), "+f"(d[3])
                 : "r"(a[0]), "r"(a[1]), "r"(a[2]), "r"(a[3]), "r"(b[0]), "r"(b[1]));
}
__device__ __forceinline__ void cp_async16(uint32_t saddr, const void* g, uint32_t srcsize) {
    asm volatile("cp.async.cg.shared.global [%0], [%1], 16, %2;"
                 :: "r"(saddr), "l"(g), "r"(srcsize));
}

// ---------------- weight conversion (fp16 hi/lo split, row-major) ----------------
__global__ void wconv_kernel(const float* __restrict__ W1, const float* __restrict__ U1,
                             const float* __restrict__ W2, const float* __restrict__ U2)
{
    const int b = blockIdx.x;
    const float* src = (b == 0) ? W1 : (b == 1) ? U1 : (b == 2) ? W2 : U2;
    __half* hi = g_wimg[b][0];
    __half* lo = g_wimg[b][1];
    for (int c = threadIdx.x; c < DIM * DIM / 8; c += blockDim.x) {
        int row = c >> 4, cc = (c & 15) * 8;
        __align__(16) __half hb[8], lb[8];
        const float4* p = (const float4*)(src + row * DIM + cc);
        float4 v0 = p[0], v1 = p[1];
        float xs[8] = {v0.x, v0.y, v0.z, v0.w, v1.x, v1.y, v1.z, v1.w};
        #pragma unroll
        for (int j = 0; j < 8; j++) {
            __half h = __float2half_rn(xs[j]);
            hb[j] = h;
            lb[j] = __float2half_rn(xs[j] - __half2float(h));
        }
        *(uint4*)(hi + row * DIM + cc) = *(const uint4*)hb;
        *(uint4*)(lo + row * DIM + cc) = *(const uint4*)lb;
    }
}

// ---------------- persistent split-output tensor-core GEMM (fp16, B 2-split) ----------------
// CTA type z (bid<148): z = h@W^T (fp16 out) + scores; zi-CTA: zi = h@U^T.
// smem fp16-elem layout: B_hi[0,17408) B_lo[17408,34816) A[34816,52224); sred after.
#define TILEW (DIM * PADS)            // 17408 elems
#define SM_BHo 0
#define SM_BLo TILEW
#define SM_Ao  (2 * TILEW)
#define SM_H_ELEMS (3 * TILEW)
#define SM_TOTAL_B (SM_H_ELEMS * 2 + 2 * TM * 2 * 4)   // 104448 + 2048 = 106496

__global__ __launch_bounds__(256, 2)
void gemm_split_kernel(int mode,                        // 0: fp32 input, 1: fp16 input
                     const float* __restrict__ hf, const __half* __restrict__ hh,
                     const __half* __restrict__ wh, const __half* __restrict__ wl,
                     const __half* __restrict__ uh, const __half* __restrict__ ul,
                     const float* __restrict__ avec,
                     __half* __restrict__ z, __half* __restrict__ zi,
                     float* __restrict__ ssrc, float* __restrict__ sdst, int n)
{
    extern __shared__ __half smem[];
    float* sred = (float*)(smem + SM_H_ELEMS);          // ss[128*2], sd[128*2]
    const int tid  = threadIdx.x;
    const int lane = tid & 31;
    const int wid  = tid >> 5;
    const uint32_t sb = smem_to_u32(smem);

    const bool isU = (blockIdx.x >= GRIDP);
    const int  t0  = blockIdx.x - (isU ? GRIDP : 0);

    // ---- load this CTA's weight pair ONCE ----
    {
        const __half* bhsrc = isU ? uh : wh;
        const __half* blsrc = isU ? ul : wl;
        for (int c = tid; c < DIM * 16; c += 256) {
            int r = c >> 4, q = (c & 15) * 8;
            *(uint4*)(smem + SM_BHo + r * PADS + q) = *(const uint4*)(bhsrc + r * DIM + q);
            *(uint4*)(smem + SM_BLo + r * PADS + q) = *(const uint4*)(blsrc + r * DIM + q);
        }
    }

    // warp tiling: 4 M-warps x 2 N-warps, warp tile 32(M)x64(N)
    const int m0 = (wid & 3) * 32;
    const int nw = wid >> 2;
    const int n0 = nw * 64;
    const int a_r = (lane & 15);
    const int a_c = (lane >> 4) * 8;
    const int b_r = ((lane >> 4) << 3) + (lane & 7);
    const int b_c = ((lane >> 3) & 1) * 8;

    __half* dst = isU ? zi : z;

    for (int t = t0; t < NT; t += GRIDP) {
        const int row0 = t * TM;

        // ---- fill A smem (fp16 single): 128 rows x 16 chunks, 8 per thread ----
        if (mode == 0) {
            #pragma unroll
            for (int i = 0; i < 8; i++) {
                int c = tid + i * 256;
                int r = c >> 4, q = (c & 15) * 8;
                int gr = row0 + r;
                __align__(16) __half hb[8];
                if (gr < n) {
                    const float4* p = (const float4*)(hf + (size_t)gr * DIM + q);
                    float4 v0 = p[0], v1 = p[1];
                    hb[0] = __float2half_rn(v0.x); hb[1] = __float2half_rn(v0.y);
                    hb[2] = __float2half_rn(v0.z); hb[3] = __float2half_rn(v0.w);
                    hb[4] = __float2half_rn(v1.x); hb[5] = __float2half_rn(v1.y);
                    hb[6] = __float2half_rn(v1.z); hb[7] = __float2half_rn(v1.w);
                } else {
                    #pragma unroll
                    for (int j = 0; j < 8; j++) hb[j] = __float2half_rn(0.f);
                }
                *(uint4*)(smem + SM_Ao + r * PADS + q) = *(const uint4*)hb;
            }
        } else {
            #pragma unroll
            for (int i = 0; i < 8; i++) {
                int c = tid + i * 256;
                int r = c >> 4, q = (c & 15) * 8;
                int gr = row0 + r;
                uint32_t saddr = sb + (uint32_t)(SM_Ao + r * PADS + q) * 2;
                cp_async16(saddr, hh + (size_t)gr * DIM + q, (gr < n) ? 16u : 0u);
            }
            asm volatile("cp.async.commit_group;" ::: "memory");
            asm volatile("cp.async.wait_group 0;" ::: "memory");
        }
        __syncthreads();

        // ---- MMA: warp tile 32x64, 2-term (A*Bh + A*Bl) ----
        float acc[2][8][4];
        #pragma unroll
        for (int mf = 0; mf < 2; mf++)
            #pragma unroll
            for (int nf = 0; nf < 8; nf++)
                #pragma unroll
                for (int q = 0; q < 4; q++) acc[mf][nf][q] = 0.f;

        #pragma unroll
        for (int ks = 0; ks < 8; ks++) {
            const int k0 = ks * 16;
            uint32_t ah[2][4];
            #pragma unroll
            for (int mf = 0; mf < 2; mf++) {
                const uint32_t aoff = (uint32_t)((m0 + mf * 16 + a_r) * PADS + k0 + a_c) * 2;
                ldsm4(ah[mf], sb + (uint32_t)SM_Ao * 2 + aoff);
            }
            #pragma unroll
            for (int np = 0; np < 4; np++) {
                const uint32_t boff = (uint32_t)((n0 + np * 16 + b_r) * PADS + k0 + b_c) * 2;
                uint32_t bh[4], bl[4];
                ldsm4(bh, sb + (uint32_t)SM_BHo * 2 + boff);
                ldsm4(bl, sb + (uint32_t)SM_BLo * 2 + boff);
                #pragma unroll
                for (int mf = 0; mf < 2; mf++) {
                    mma16816h(acc[mf][2 * np + 0], ah[mf], &bh[0]);
                    mma16816h(acc[mf][2 * np + 0], ah[mf], &bl[0]);
                    mma16816h(acc[mf][2 * np + 1], ah[mf], &bh[2]);
                    mma16816h(acc[mf][2 * np + 1], ah[mf], &bl[2]);
                }
            }
        }

        // ---- epilogue: fp16 STG ----
        #pragma unroll
        for (int mf = 0; mf < 2; mf++) {
            const int mA = row0 + m0 + mf * 16 + (lane >> 2);
            #pragma unroll
            for (int nf = 0; nf < 8; nf++) {
                const int c = n0 + nf * 8 + (lane & 3) * 2;
                if (mA < n)
                    *(__half2*)(dst + (size_t)mA * DIM + c) =
                        __floats2half2_rn(acc[mf][nf][0], acc[mf][nf][1]);
                if (mA + 8 < n)
                    *(__half2*)(dst + (size_t)(mA + 8) * DIM + c) =
                        __floats2half2_rn(acc[mf][nf][2], acc[mf][nf][3]);
            }
        }

        // ---- scores from z accumulators (z-CTAs only, fp32 exact) ----
        if (!isU) {
            #pragma unroll
            for (int mf = 0; mf < 2; mf++) {
                float s0 = 0.f, s1 = 0.f, d0 = 0.f, d1 = 0.f;
                #pragma unroll
                for (int nf = 0; nf < 8; nf++) {
                    const int c = n0 + nf * 8 + (lane & 3) * 2;
                    const float a0 = avec[c], a1 = avec[c + 1];
                    const float e0 = avec[DIM + c], e1 = avec[DIM + c + 1];
                    s0 += acc[mf][nf][0] * a0 + acc[mf][nf][1] * a1;
                    s1 += acc[mf][nf][2] * a0 + acc[mf][nf][3] * a1;
                    d0 += acc[mf][nf][0] * e0 + acc[mf][nf][1] * e1;
                    d1 += acc[mf][nf][2] * e0 + acc[mf][nf][3] * e1;
                }
                #pragma unroll
                for (int o = 1; o <= 2; o <<= 1) {
                    s0 += __shfl_xor_sync(0xffffffffu, s0, o);
                    s1 += __shfl_xor_sync(0xffffffffu, s1, o);
                    d0 += __shfl_xor_sync(0xffffffffu, d0, o);
                    d1 += __shfl_xor_sync(0xffffffffu, d1, o);
                }
                if ((lane & 3) == 0) {
                    const int lr = m0 + mf * 16 + (lane >> 2);
                    sred[lr * 2 + nw]                = s0;
                    sred[(lr + 8) * 2 + nw]          = s1;
                    sred[TM * 2 + lr * 2 + nw]       = d0;
                    sred[TM * 2 + (lr + 8) * 2 + nw] = d1;
                }
            }
        }
        __syncthreads();   // protects A smem overwrite AND sred

        if (!isU && tid < TM) {
            const int r = row0 + tid;
            if (r < n) {
                ssrc[r] = sred[tid * 2 + 0] + sred[tid * 2 + 1];
                sdst[r] = sred[TM * 2 + tid * 2 + 0] + sred[TM * 2 + tid * 2 + 1];
            }
        }
    }
}

// ---------------- attention + aggregation (fp16 gather) ----------------
__global__ __launch_bounds__(256)
void attn_agg_kernel(const __half* __restrict__ z, const __half* __restrict__ zi,
                     const float* __restrict__ ssrc, const float* __restrict__ sdst,
                     const float* __restrict__ edge_d, const int* __restrict__ edge_src,
                     const float* __restrict__ Wv, const float* __restrict__ avec,
                     int toHalf, __half* __restrict__ outH, float* __restrict__ outF, int n)
{
    const int node = (blockIdx.x * blockDim.x + threadIdx.x) >> 5;
    const int lane = threadIdx.x & 31;
    if (node >= n) return;

    const float c = Wv[0] * avec[2 * DIM];

    int   src = 0;
    float sc  = -1e30f;
    if (lane < DEG) {
        int e = node * DEG + lane;
        src   = edge_src[e];
        float s = ssrc[src] + sdst[node] + c * edge_d[e];
        sc = (s >= 0.f) ? s : 0.01f * s;
    }
    float m = sc;
    #pragma unroll
    for (int o = 8; o > 0; o >>= 1) m = fmaxf(m, __shfl_xor_sync(0xffffffffu, m, o));
    float ex = (lane < DEG) ? __expf(sc - m) : 0.f;
    float ssum = ex;
    #pragma unroll
    for (int o = 8; o > 0; o >>= 1) ssum += __shfl_xor_sync(0xffffffffu, ssum, o);
    float alpha = ex / ssum;

    float al[DEG];
    int   sr[DEG];
    #pragma unroll
    for (int e = 0; e < DEG; e++) {
        al[e] = __shfl_sync(0xffffffffu, alpha, e);
        sr[e] = __shfl_sync(0xffffffffu, src,   e);
    }

    float4 acc;
    {
        uint2 v = *((const uint2*)(zi + (size_t)node * DIM) + lane);
        float2 f0 = __half22float2(*(__half2*)&v.x);
        float2 f1 = __half22float2(*(__half2*)&v.y);
        acc = make_float4(f0.x, f0.y, f1.x, f1.y);
    }
    #pragma unroll
    for (int e = 0; e < DEG; e++) {
        uint2 v = *((const uint2*)(z + (size_t)sr[e] * DIM) + lane);
        float2 f0 = __half22float2(*(__half2*)&v.x);
        float2 f1 = __half22float2(*(__half2*)&v.y);
        acc.x = fmaf(al[e], f0.x, acc.x);
        acc.y = fmaf(al[e], f0.y, acc.y);
        acc.z = fmaf(al[e], f1.x, acc.z);
        acc.w = fmaf(al[e], f1.y, acc.w);
    }
    acc.x = fmaxf(acc.x, 0.f);
    acc.y = fmaxf(acc.y, 0.f);
    acc.z = fmaxf(acc.z, 0.f);
    acc.w = fmaxf(acc.w, 0.f);

    if (toHalf) {
        uint2 v;
        __half2 p0 = __floats2half2_rn(acc.x, acc.y);
        __half2 p1 = __floats2half2_rn(acc.z, acc.w);
        v.x = *(uint32_t*)&p0;
        v.y = *(uint32_t*)&p1;
        *((uint2*)(outH + (size_t)node * DIM) + lane) = v;
    } else {
        *(float4*)(outF + (size_t)node * DIM + lane * 4) = acc;
    }
}

extern "C" void kernel_launch(void* const* d_in, const int* in_sizes, int n_in,
                              void* d_out, int out_size)
{
    const float* attr   = (const float*)d_in[0];
    const float* edge_d = (const float*)d_in[1];
    const float* Wv1    = (const float*)d_in[2];
    const float* Ww1    = (const float*)d_in[3];
    const float* Wu1    = (const float*)d_in[4];
    const float* Wa1    = (const float*)d_in[5];
    const float* Wv2    = (const float*)d_in[6];
    const float* Ww2    = (const float*)d_in[7];
    const float* Wu2    = (const float*)d_in[8];
    const float* Wa2    = (const float*)d_in[9];
    const int*   esrc   = (const int*)d_in[10];
    float*       out    = (float*)d_out;

    float *ssp, *sdp;
    __half *zp, *zip, *h1p, *wb;
    cudaGetSymbolAddress((void**)&zp,  g_z);
    cudaGetSymbolAddress((void**)&zip, g_zi);
    cudaGetSymbolAddress((void**)&h1p, g_h1);
    cudaGetSymbolAddress((void**)&ssp, g_ssrc);
    cudaGetSymbolAddress((void**)&sdp, g_sdst);
    cudaGetSymbolAddress((void**)&wb,  g_wimg);

    const __half* w1h = wb + (size_t)0 * DIM * DIM;
    const __half* w1l = wb + (size_t)1 * DIM * DIM;
    const __half* u1h = wb + (size_t)2 * DIM * DIM;
    const __half* u1l = wb + (size_t)3 * DIM * DIM;
    const __half* w2h = wb + (size_t)4 * DIM * DIM;
    const __half* w2l = wb + (size_t)5 * DIM * DIM;
    const __half* u2h = wb + (size_t)6 * DIM * DIM;
    const __half* u2l = wb + (size_t)7 * DIM * DIM;

    cudaFuncSetAttribute(gemm_split_kernel,
                         cudaFuncAttributeMaxDynamicSharedMemorySize, SM_TOTAL_B);

    const int grid_a = (NN * 32 + 255) / 256;     // 12500

    wconv_kernel<<<4, 256>>>(Ww1, Wu1, Ww2, Wu2);

    gemm_split_kernel<<<2 * GRIDP, 256, SM_TOTAL_B>>>(0, attr, nullptr,
                                                      w1h, w1l, u1h, u1l, Wa1,
                                                      zp, zip, ssp, sdp, NN);
    attn_agg_kernel<<<grid_a, 256>>>(zp, zip, ssp, sdp, edge_d, esrc, Wv1, Wa1,
                                     1, h1p, nullptr, NN);

    gemm_split_kernel<<<2 * GRIDP, 256, SM_TOTAL_B>>>(1, nullptr, h1p,
                                                      w2h, w2l, u2h, u2l, Wa2,
                                                      zp, zip, ssp, sdp, NN);
    attn_agg_kernel<<<grid_a, 256>>>(zp, zip, ssp, sdp, edge_d, esrc, Wv2, Wa2,
                                     0, nullptr, out, NN);
}